// round 12
// baseline (speedup 1.0000x reference)
#include <cuda_runtime.h>
#include <cuda_bf16.h>

typedef unsigned int u32;
typedef unsigned long long u64;

#define N_ROWS 2048
#define K_CODES 81920
#define C_DIM 64
#define CEXT 80                    // 64 data + 1 enorm-fold + 15 zero pad
#define M_TILE 128
#define N_TILE 128
#define CHUNK 1024
#define TILES (CHUNK / N_TILE)     // 8
#define NCHUNKS (K_CODES / CHUNK)  // 80
#define PITCHB 176                 // bytes per smem row (88 bf16; conflict-free)
#define CAP 2048

// smem offsets: A 0..22528, B0 22528, B1 45056, sMin 67584
#define A_OFF 0
#define B0_OFF 22528
#define B1_OFF 45056
#define SMIN_OFF 67584
#define SMEM_TOTAL 68608

// ---------------- device scratch (no allocation allowed) -------------------
__device__ __nv_bfloat16 g_zbf[N_ROWS * CEXT];   // [r][0..63]=z, [64]=1.0, pad 0
__device__ __nv_bfloat16 g_ebf[K_CODES * CEXT];  // [k][0..63]=e, [64]=-enorm/2, pad 0
__device__ float g_enorm[K_CODES];
__device__ float g_znorm[N_ROWS];
__device__ float g_sumabs[N_ROWS];
__device__ u32 g_smin[N_ROWS];     // orderable-uint float
__device__ u32 g_emax;             // bits of max|emb|
__device__ int g_cnt[N_ROWS];
__device__ int g_cand[N_ROWS * CAP];
__device__ double g_rowloss[N_ROWS];

// ---------------- helpers ---------------------------------------------------
__device__ __forceinline__ u32 f2o(float f) {
    u32 b = __float_as_uint(f);
    return (b & 0x80000000u) ? ~b : (b | 0x80000000u);
}
__device__ __forceinline__ float o2f(u32 o) {
    u32 b = (o & 0x80000000u) ? (o ^ 0x80000000u) : ~o;
    return __uint_as_float(b);
}
__device__ __forceinline__ u32 smem_u32(const void* p) {
    u32 a; asm("{ .reg .u64 t; cvta.to.shared.u64 t, %1; cvt.u32.u64 %0, t; }"
               : "=r"(a) : "l"(p));
    return a;
}
__device__ __forceinline__ void cpa16(u32 dst, const void* src) {
    asm volatile("cp.async.cg.shared.global [%0], [%1], 16;" :: "r"(dst), "l"(src));
}
__device__ __forceinline__ void cpa_commit() { asm volatile("cp.async.commit_group;"); }
template <int N> __device__ __forceinline__ void cpa_wait() {
    asm volatile("cp.async.wait_group %0;" :: "n"(N));
}
__device__ __forceinline__ void ldsm4(u32* r, u32 addr) {
    asm volatile("ldmatrix.sync.aligned.m8n8.x4.shared.b16 {%0,%1,%2,%3}, [%4];"
                 : "=r"(r[0]), "=r"(r[1]), "=r"(r[2]), "=r"(r[3]) : "r"(addr));
}
__device__ __forceinline__ void mma16816(float* d, const u32* a, u32 b0, u32 b1) {
    asm volatile(
        "mma.sync.aligned.m16n8k16.row.col.f32.bf16.bf16.f32 "
        "{%0,%1,%2,%3},{%4,%5,%6,%7},{%8,%9},{%0,%1,%2,%3};"
        : "+f"(d[0]), "+f"(d[1]), "+f"(d[2]), "+f"(d[3])
        : "r"(a[0]), "r"(a[1]), "r"(a[2]), "r"(a[3]), "r"(b0), "r"(b1));
}

// ---------------------------------------------------------------------------
// Prep — R8 math verbatim; additionally writes the extended column 64
// (A: 1.0, B: -enorm/2 in bf16; error <= enorm*2^-9 ~ 1e-11, absorbed by
// the 2e-6 margin slack) and zero padding 65..79.
// ---------------------------------------------------------------------------
__global__ void vq_prep(const float* __restrict__ z, const float* __restrict__ emb) {
    __shared__ float sMax[256];
    int tid = threadIdx.x;
    int t = blockIdx.x * 256 + tid;
    float lmax = 0.f;
    if (t < K_CODES) {
        const float* e = emb + (size_t)t * C_DIM;
        __nv_bfloat16* dst = g_ebf + (size_t)t * CEXT;
        float s = 0.f;
#pragma unroll
        for (int c = 0; c < C_DIM; ++c) {
            float v = e[c];
            s = fmaf(v, v, s);
            lmax = fmaxf(lmax, fabsf(v));
            dst[c] = __float2bfloat16_rn(v);
        }
        g_enorm[t] = s;
        dst[64] = __float2bfloat16_rn(-0.5f * s);
#pragma unroll
        for (int c = 65; c < CEXT; ++c) dst[c] = __float2bfloat16_rn(0.f);
    } else if (t < K_CODES + N_ROWS) {
        int r = t - K_CODES;
        const float* zr = z + (size_t)r * C_DIM;
        __nv_bfloat16* dst = g_zbf + (size_t)r * CEXT;
        float s = 0.f, sa = 0.f;
#pragma unroll
        for (int c = 0; c < C_DIM; ++c) {
            float v = zr[c];
            s = fmaf(v, v, s);
            sa += fabsf(v);
            dst[c] = __float2bfloat16_rn(v);
        }
        g_znorm[r] = s;
        g_sumabs[r] = sa;
        dst[64] = __float2bfloat16_rn(1.0f);
#pragma unroll
        for (int c = 65; c < CEXT; ++c) dst[c] = __float2bfloat16_rn(0.f);
        g_smin[r] = 0xFFFFFFFFu;
        g_cnt[r] = 0;
    }
    sMax[tid] = lmax;
    __syncthreads();
#pragma unroll
    for (int st = 128; st >= 1; st >>= 1) {
        if (tid < st) sMax[tid] = fmaxf(sMax[tid], sMax[tid + st]);
        __syncthreads();
    }
    if (tid == 0 && sMax[0] > 0.f) atomicMax(&g_emax, __float_as_uint(sMax[0]));
}

// ---------------------------------------------------------------------------
// Two-pass bf16 HMMA filter with enorm folded into K-step 4:
//   MMA accumulator d = dot - enorm/2, so s = -2*d (exact scaling).
// pass=0: per-row MAX of d -> g_smin = f2o(-2*maxd).
// pass=1: collect d >= dthr = -0.5*(smin+margin)  (exactly equiv to s<=thr).
// Both passes run the identical MMA sequence -> identical d values.
// ---------------------------------------------------------------------------
__global__ __launch_bounds__(256, 2) void vq_mma_pass(int pass) {
    extern __shared__ char smem[];
    const u32 sbase = smem_u32(smem);
    float* sMin = (float*)(smem + SMIN_OFF);

    const int tid = threadIdx.x, lane = tid & 31, wid = tid >> 5;
    const int warp_m = wid >> 1, warp_n = wid & 1;
    const int g = lane >> 2, tq = lane & 3;
    const int rowBase = blockIdx.y * M_TILE;
    const int kChunk = blockIdx.x * CHUNK;

    // group 0: A tile + B tile 0 (128 rows x 10 chunks of 16B each)
#pragma unroll
    for (int j = 0; j < 5; ++j) {
        int idx = tid + 256 * j;
        int r = idx / 10, sg = idx % 10;
        cpa16(sbase + A_OFF + r * PITCHB + sg * 16,
              g_zbf + (size_t)(rowBase + r) * CEXT + sg * 8);
        cpa16(sbase + B0_OFF + r * PITCHB + sg * 16,
              g_ebf + (size_t)(kChunk + r) * CEXT + sg * 8);
    }
    cpa_commit();

    float dthr[2][2], runmax[2][2];
#pragma unroll
    for (int am = 0; am < 2; ++am)
#pragma unroll
        for (int h = 0; h < 2; ++h) {
            runmax[am][h] = __int_as_float(0xFF800000);  // -inf
            if (pass) {
                int r = rowBase + warp_m * 32 + am * 16 + g + 8 * h;
                float smin = o2f(g_smin[r]);
                float emax = __uint_as_float(g_emax);
                float margin = 4.0f * 0.0082f * emax * g_sumabs[r]
                             + g_znorm[r] * 9.5367431640625e-07f + 2e-6f;
                dthr[am][h] = -0.5f * (smin + margin);
            } else dthr[am][h] = 0.f;
        }

    // ldmatrix lane base addresses (R5/R11-proven mapping, pitch 176)
    u32 aoff[2];
#pragma unroll
    for (int am = 0; am < 2; ++am)
        aoff[am] = sbase + A_OFF
                 + (u32)(warp_m * 32 + am * 16 + (lane & 15)) * PITCHB
                 + ((lane >> 4) & 1) * 16;
    const u32 boffl = (u32)(warp_n * 64 + ((lane >> 4) << 3) + (lane & 7)) * PITCHB
                    + ((lane >> 3) & 1) * 16;

    for (int t = 0; t < TILES; ++t) {
        int buf = t & 1;
        if (t + 1 < TILES) {
            u32 db = sbase + (((t + 1) & 1) ? B1_OFF : B0_OFF);
            const __nv_bfloat16* src =
                g_ebf + (size_t)(kChunk + (t + 1) * N_TILE) * CEXT;
#pragma unroll
            for (int j = 0; j < 5; ++j) {
                int idx = tid + 256 * j;
                int r = idx / 10, sg = idx % 10;
                cpa16(db + r * PITCHB + sg * 16, src + (size_t)r * CEXT + sg * 8);
            }
            cpa_commit();
            cpa_wait<1>();
        } else {
            cpa_wait<0>();
        }
        __syncthreads();

        const u32 Bb = sbase + (buf ? B1_OFF : B0_OFF);

        float d[2][8][4];
#pragma unroll
        for (int am = 0; am < 2; ++am)
#pragma unroll
            for (int bn = 0; bn < 8; ++bn)
#pragma unroll
                for (int e = 0; e < 4; ++e) d[am][bn][e] = 0.f;

#pragma unroll
        for (int ks = 0; ks < 5; ++ks) {
            u32 aa[2][4];
            ldsm4(aa[0], aoff[0] + ks * 32);
            ldsm4(aa[1], aoff[1] + ks * 32);
#pragma unroll
            for (int bp = 0; bp < 4; ++bp) {
                u32 bb[4];
                ldsm4(bb, Bb + boffl + bp * (16 * PITCHB) + ks * 32);
                mma16816(d[0][2 * bp],     aa[0], bb[0], bb[1]);
                mma16816(d[0][2 * bp + 1], aa[0], bb[2], bb[3]);
                mma16816(d[1][2 * bp],     aa[1], bb[0], bb[1]);
                mma16816(d[1][2 * bp + 1], aa[1], bb[2], bb[3]);
            }
        }

        // epilogue: 1 op per element
        if (!pass) {
#pragma unroll
            for (int am = 0; am < 2; ++am)
#pragma unroll
                for (int bn = 0; bn < 8; ++bn)
#pragma unroll
                    for (int e = 0; e < 4; ++e)
                        runmax[am][e >> 1] = fmaxf(runmax[am][e >> 1],
                                                   d[am][bn][e]);
        } else {
#pragma unroll
            for (int am = 0; am < 2; ++am)
#pragma unroll
                for (int bn = 0; bn < 8; ++bn)
#pragma unroll
                    for (int e = 0; e < 4; ++e) {
                        if (d[am][bn][e] >= dthr[am][e >> 1]) {
                            int col = warp_n * 64 + bn * 8 + 2 * tq + (e & 1);
                            int row = rowBase + warp_m * 32 + am * 16 + g
                                    + 8 * (e >> 1);
                            int k = kChunk + t * N_TILE + col;
                            int ix = atomicAdd(&g_cnt[row], 1);
                            if (ix < CAP) g_cand[(size_t)row * CAP + ix] = k;
                        }
                    }
        }
        __syncthreads();
    }

    if (!pass) {
#pragma unroll
        for (int am = 0; am < 2; ++am)
#pragma unroll
            for (int h = 0; h < 2; ++h) {
                float v = runmax[am][h];
                v = fmaxf(v, __shfl_xor_sync(0xFFFFFFFFu, v, 1));
                v = fmaxf(v, __shfl_xor_sync(0xFFFFFFFFu, v, 2));
                if (tq == 0) {
                    int r = warp_m * 32 + am * 16 + g + 8 * h;
                    sMin[r * 2 + warp_n] = v;
                }
            }
        __syncthreads();
        if (tid < M_TILE) {
            float v = fmaxf(sMin[tid * 2], sMin[tid * 2 + 1]);
            atomicMin(&g_smin[rowBase + tid], f2o(-2.0f * v));  // s = -2*maxd
        }
    }
}

// ---------------------------------------------------------------------------
// Rescore exactly (R8 VERBATIM — proven).
// ---------------------------------------------------------------------------
__global__ void vq_rescore_finalize(const float* __restrict__ z,
                                    const float* __restrict__ emb,
                                    float* __restrict__ out, int out_size) {
    __shared__ float sZ[2][C_DIM];
    __shared__ u64 sBest[8];
    __shared__ u64 sFinal[2];
    int tid = threadIdx.x, lane = tid & 31, w = tid >> 5;
    int rowBlk = blockIdx.x * 2;
    if (tid < 2 * C_DIM)
        sZ[tid >> 6][tid & 63] = z[(size_t)(rowBlk + (tid >> 6)) * C_DIM + (tid & 63)];
    __syncthreads();

    int wr = w >> 2, wi = w & 3;
    int row = rowBlk + wr;
    float znorm = g_znorm[row];
    int cnt = g_cnt[row];
    const float* zr = sZ[wr];
    u64 best = 0xFFFFFFFFFFFFFFFFull;

    if (cnt <= CAP) {
        for (int i = wi * 32 + lane; i < cnt; i += 128) {
            int k = g_cand[(size_t)row * CAP + i];
            const float* e = emb + (size_t)k * C_DIM;
            float dot = 0.f;
#pragma unroll
            for (int c = 0; c < C_DIM; ++c) dot = fmaf(zr[c], e[c], dot);
            float d2 = __fadd_rn(__fsub_rn(znorm, __fmul_rn(2.0f, dot)), g_enorm[k]);
            u64 p = ((u64)f2o(d2) << 32) | (u32)k;
            best = p < best ? p : best;
        }
    } else {  // overflow fallback: exact full scan (correctness net)
        for (int k = wi * 32 + lane; k < K_CODES; k += 128) {
            const float* e = emb + (size_t)k * C_DIM;
            float dot = 0.f;
#pragma unroll
            for (int c = 0; c < C_DIM; ++c) dot = fmaf(zr[c], e[c], dot);
            float d2 = __fadd_rn(__fsub_rn(znorm, __fmul_rn(2.0f, dot)), g_enorm[k]);
            u64 p = ((u64)f2o(d2) << 32) | (u32)k;
            best = p < best ? p : best;
        }
    }
#pragma unroll
    for (int st = 16; st >= 1; st >>= 1) {
        u64 o = __shfl_xor_sync(0xFFFFFFFFu, best, st);
        best = o < best ? o : best;
    }
    if (lane == 0) sBest[w] = best;
    __syncthreads();
    if (tid < 2) {
        u64 m = sBest[tid * 4];
#pragma unroll
        for (int q = 1; q < 4; ++q) m = sBest[tid * 4 + q] < m ? sBest[tid * 4 + q] : m;
        sFinal[tid] = m;
    }
    __syncthreads();

    if (wi == 0) {
        u32 idx = (u32)sFinal[wr];
        double part = 0.0;
#pragma unroll
        for (int q = 0; q < 2; ++q) {
            int c = lane + 32 * q;
            float e = emb[(size_t)idx * C_DIM + c];
            float zv = zr[c];
            if ((size_t)row * C_DIM + c < (size_t)out_size)
                out[(size_t)row * C_DIM + c] = __fadd_rn(zv, __fsub_rn(e, zv));
            float s = __fsub_rn(zv, e);
            part += (double)__fmul_rn(s, s);
        }
#pragma unroll
        for (int st = 16; st >= 1; st >>= 1)
            part += __shfl_xor_sync(0xFFFFFFFFu, part, st);
        if (lane == 0) {
            g_rowloss[row] = part;
            if (out_size >= 133122) out[131074 + row] = (float)idx;
        }
    }
}

__global__ void vq_loss(float* __restrict__ out, int out_size) {
    __shared__ double sD[256];
    int tid = threadIdx.x;
    double v[8];
#pragma unroll
    for (int q = 0; q < 8; ++q) v[q] = g_rowloss[tid + 256 * q];
    double s = 0.0;
#pragma unroll
    for (int q = 0; q < 8; ++q) s += v[q];
    sD[tid] = s;
    __syncthreads();
#pragma unroll
    for (int st = 128; st >= 1; st >>= 1) {
        if (tid < st) sD[tid] += sD[tid + st];
        __syncthreads();
    }
    if (tid == 0 && out_size >= 133122) {
        float m = (float)(sD[0] / 131072.0);
        out[131072] = m;
        out[131073] = m;
    }
}

// ---------------------------------------------------------------------------
extern "C" void kernel_launch(void* const* d_in, const int* in_sizes, int n_in,
                              void* d_out, int out_size) {
    const float* z = (const float*)d_in[0];
    const float* emb = (const float*)d_in[1];
    if (n_in >= 2 && in_sizes[0] == K_CODES * C_DIM && in_sizes[1] == N_ROWS * C_DIM) {
        const float* t = z; z = emb; emb = t;
    }
    float* out = (float*)d_out;

    cudaFuncSetAttribute(vq_mma_pass,
                         cudaFuncAttributeMaxDynamicSharedMemorySize, SMEM_TOTAL);

    vq_prep<<<(K_CODES + N_ROWS) / 256, 256>>>(z, emb);
    vq_mma_pass<<<dim3(NCHUNKS, N_ROWS / M_TILE), 256, SMEM_TOTAL>>>(0);
    vq_mma_pass<<<dim3(NCHUNKS, N_ROWS / M_TILE), 256, SMEM_TOTAL>>>(1);
    vq_rescore_finalize<<<N_ROWS / 2, 256>>>(z, emb, out, out_size);
    vq_loss<<<1, 256>>>(out, out_size);
}

// round 13
// speedup vs baseline: 1.0077x; 1.0077x over previous
#include <cuda_runtime.h>
#include <cuda_bf16.h>

typedef unsigned int u32;
typedef unsigned long long u64;

#define N_ROWS 2048
#define K_CODES 81920
#define C_DIM 64
#define M_TILE 128
#define N_TILE 128
#define CHUNK 1024
#define TILES (CHUNK / N_TILE)     // 8
#define NCHUNKS (K_CODES / CHUNK)  // 80
#define NCHUNKS_SEED 16            // seed pass: codes 0..16383, ~one wave
#define PITCHB 144                 // bytes per smem row (72 bf16, conflict-free)
#define CAP 2048

// ---------------- device scratch (no allocation allowed) -------------------
__device__ __nv_bfloat16 g_zbf[N_ROWS * C_DIM];
__device__ __nv_bfloat16 g_ebf[K_CODES * C_DIM];
__device__ float g_enorm[K_CODES];
__device__ float g_znorm[N_ROWS];
__device__ float g_sumabs[N_ROWS];
__device__ u32 g_smin[N_ROWS];     // orderable-uint float (monotone decreasing)
__device__ u32 g_emax;             // bits of max|emb|
__device__ int g_cnt[N_ROWS];
__device__ int g_cand[N_ROWS * CAP];
__device__ double g_rowloss[N_ROWS];

// ---------------- helpers ---------------------------------------------------
__device__ __forceinline__ u32 f2o(float f) {
    u32 b = __float_as_uint(f);
    return (b & 0x80000000u) ? ~b : (b | 0x80000000u);
}
__device__ __forceinline__ float o2f(u32 o) {
    u32 b = (o & 0x80000000u) ? (o ^ 0x80000000u) : ~o;
    return __uint_as_float(b);
}
__device__ __forceinline__ u32 smem_u32(const void* p) {
    u32 a; asm("{ .reg .u64 t; cvta.to.shared.u64 t, %1; cvt.u32.u64 %0, t; }"
               : "=r"(a) : "l"(p));
    return a;
}
__device__ __forceinline__ void cpa16(u32 dst, const void* src) {
    asm volatile("cp.async.cg.shared.global [%0], [%1], 16;" :: "r"(dst), "l"(src));
}
__device__ __forceinline__ void cpa_commit() { asm volatile("cp.async.commit_group;"); }
template <int N> __device__ __forceinline__ void cpa_wait() {
    asm volatile("cp.async.wait_group %0;" :: "n"(N));
}
__device__ __forceinline__ void ldsm4(u32* r, u32 addr) {
    asm volatile("ldmatrix.sync.aligned.m8n8.x4.shared.b16 {%0,%1,%2,%3}, [%4];"
                 : "=r"(r[0]), "=r"(r[1]), "=r"(r[2]), "=r"(r[3]) : "r"(addr));
}
__device__ __forceinline__ void mma16816(float* d, const u32* a, u32 b0, u32 b1) {
    asm volatile(
        "mma.sync.aligned.m16n8k16.row.col.f32.bf16.bf16.f32 "
        "{%0,%1,%2,%3},{%4,%5,%6,%7},{%8,%9},{%0,%1,%2,%3};"
        : "+f"(d[0]), "+f"(d[1]), "+f"(d[2]), "+f"(d[3])
        : "r"(a[0]), "r"(a[1]), "r"(a[2]), "r"(a[3]), "r"(b0), "r"(b1));
}

// ---------------------------------------------------------------------------
// Prep — R8 VERBATIM (proven-fast configuration).
// ---------------------------------------------------------------------------
__global__ void vq_prep(const float* __restrict__ z, const float* __restrict__ emb) {
    __shared__ float sMax[256];
    int tid = threadIdx.x;
    int t = blockIdx.x * 256 + tid;
    float lmax = 0.f;
    if (t < K_CODES) {
        const float* e = emb + (size_t)t * C_DIM;
        float s = 0.f;
#pragma unroll
        for (int c = 0; c < C_DIM; ++c) {
            float v = e[c];
            s = fmaf(v, v, s);
            lmax = fmaxf(lmax, fabsf(v));
            g_ebf[(size_t)t * C_DIM + c] = __float2bfloat16_rn(v);
        }
        g_enorm[t] = s;
    } else if (t < K_CODES + N_ROWS) {
        int r = t - K_CODES;
        const float* zr = z + (size_t)r * C_DIM;
        float s = 0.f, sa = 0.f;
#pragma unroll
        for (int c = 0; c < C_DIM; ++c) {
            float v = zr[c];
            s = fmaf(v, v, s);
            sa += fabsf(v);
            g_zbf[(size_t)r * C_DIM + c] = __float2bfloat16_rn(v);
        }
        g_znorm[r] = s;
        g_sumabs[r] = sa;
        g_smin[r] = 0xFFFFFFFFu;
        g_cnt[r] = 0;
    }
    sMax[tid] = lmax;
    __syncthreads();
#pragma unroll
    for (int st = 128; st >= 1; st >>= 1) {
        if (tid < st) sMax[tid] = fmaxf(sMax[tid], sMax[tid + st]);
        __syncthreads();
    }
    if (tid == 0 && sMax[0] > 0.f) atomicMax(&g_emax, __float_as_uint(sMax[0]));
}

// ---------------------------------------------------------------------------
// bf16 HMMA filter — R11 inner loop (ldmatrix, measured-best).
// pass=0 (sub-grid, NCHUNKS_SEED chunks): per-row min of s -> g_smin seed.
// pass=1 (full grid, ONE pass): collect s <= thr with PER-TILE refreshed
//   thresholds from g_smin (smem-staged; monotone tightening as CTAs finish
//   and atomicMin their own mins back). Any snapshot of g_smin >= true min,
//   so collected set is always a superset of the required set -> exact
//   rescore yields the identical argmin.
// ---------------------------------------------------------------------------
__global__ __launch_bounds__(256, 2) void vq_mma_pass(int pass) {
    extern __shared__ char smem[];
    const u32 sbase = smem_u32(smem);
    // offsets: A 0..18432, B0 18432, B1 36864, En0 55296, En1 55808,
    //          sMar 56320 (512B), sThr 56832 (512B); sMin reuses 56320 post-loop
    float* sMar = (float*)(smem + 56320);
    float* sThr = (float*)(smem + 56832);
    float* sMin = (float*)(smem + 56320);

    const int tid = threadIdx.x, lane = tid & 31, wid = tid >> 5;
    const int warp_m = wid >> 1, warp_n = wid & 1;
    const int g = lane >> 2, tq = lane & 3;
    const int rowBase = blockIdx.y * M_TILE;
    const int kChunk = blockIdx.x * CHUNK;

    // group 0: A tile + B tile 0 + En0
#pragma unroll
    for (int j = 0; j < 4; ++j) {
        int idx = tid + 256 * j, r = idx >> 3, sg = idx & 7;
        cpa16(sbase + r * PITCHB + sg * 16,
              g_zbf + (size_t)(rowBase + r) * C_DIM + sg * 8);
        cpa16(sbase + 18432 + r * PITCHB + sg * 16,
              g_ebf + (size_t)(kChunk + r) * C_DIM + sg * 8);
    }
    if (tid < 32) cpa16(sbase + 55296 + tid * 16, g_enorm + kChunk + tid * 4);
    cpa_commit();

    // per-row margins into smem (pass 1 only); same tid later composes sThr
    if (pass && tid < M_TILE) {
        int r = rowBase + tid;
        sMar[tid] = 4.0f * 0.0082f * __uint_as_float(g_emax) * g_sumabs[r]
                  + g_znorm[r] * 9.5367431640625e-07f + 2e-6f;
    }

    float runmin[2][2];
#pragma unroll
    for (int am = 0; am < 2; ++am)
#pragma unroll
        for (int h = 0; h < 2; ++h) runmin[am][h] = __int_as_float(0x7F800000);

    // ldmatrix lane base addresses (R5/R11-proven mapping)
    u32 aoff[2];
#pragma unroll
    for (int am = 0; am < 2; ++am)
        aoff[am] = sbase + (u32)(warp_m * 32 + am * 16 + (lane & 15)) * PITCHB
                 + ((lane >> 4) & 1) * 16;
    const u32 boffl = (u32)(warp_n * 64 + ((lane >> 4) << 3) + (lane & 7)) * PITCHB
                    + ((lane >> 3) & 1) * 16;

    for (int t = 0; t < TILES; ++t) {
        int buf = t & 1;
        if (t + 1 < TILES) {
            u32 db = sbase + (((t + 1) & 1) ? 36864u : 18432u);
            const __nv_bfloat16* src =
                g_ebf + (size_t)(kChunk + (t + 1) * N_TILE) * C_DIM;
#pragma unroll
            for (int j = 0; j < 4; ++j) {
                int idx = tid + 256 * j, r = idx >> 3, sg = idx & 7;
                cpa16(db + r * PITCHB + sg * 16, src + (size_t)r * C_DIM + sg * 8);
            }
            if (tid < 32)
                cpa16(sbase + (((t + 1) & 1) ? 55808u : 55296u) + tid * 16,
                      g_enorm + kChunk + (t + 1) * N_TILE + tid * 4);
            cpa_commit();
            cpa_wait<1>();
        } else {
            cpa_wait<0>();
        }

        // per-tile threshold refresh (stale smin only enlarges thr -> sound)
        if (pass && tid < M_TILE)
            sThr[tid] = o2f(__ldcg(&g_smin[rowBase + tid])) + sMar[tid];
        __syncthreads();

        const u32 Bb = sbase + (buf ? 36864u : 18432u);
        const float* En = (const float*)(smem + (buf ? 55808 : 55296));

        float d[2][8][4];
#pragma unroll
        for (int am = 0; am < 2; ++am)
#pragma unroll
            for (int bn = 0; bn < 8; ++bn)
#pragma unroll
                for (int e = 0; e < 4; ++e) d[am][bn][e] = 0.f;

#pragma unroll
        for (int ks = 0; ks < 4; ++ks) {
            u32 aa[2][4];
            ldsm4(aa[0], aoff[0] + ks * 32);
            ldsm4(aa[1], aoff[1] + ks * 32);
#pragma unroll
            for (int bp = 0; bp < 4; ++bp) {
                u32 bb[4];
                ldsm4(bb, Bb + boffl + bp * (16 * PITCHB) + ks * 32);
                mma16816(d[0][2 * bp],     aa[0], bb[0], bb[1]);
                mma16816(d[0][2 * bp + 1], aa[0], bb[2], bb[3]);
                mma16816(d[1][2 * bp],     aa[1], bb[0], bb[1]);
                mma16816(d[1][2 * bp + 1], aa[1], bb[2], bb[3]);
            }
        }

        if (!pass) {
            // seed pass: running min only
#pragma unroll
            for (int am = 0; am < 2; ++am)
#pragma unroll
                for (int bn = 0; bn < 8; ++bn)
#pragma unroll
                    for (int e = 0; e < 4; ++e) {
                        int col = warp_n * 64 + bn * 8 + 2 * tq + (e & 1);
                        float s = __fsub_rn(En[col],
                                            __fmul_rn(2.0f, d[am][bn][e]));
                        runmin[am][e >> 1] = fminf(runmin[am][e >> 1], s);
                    }
        } else {
            // collection pass: thresholds from smem (short-lived regs only)
            float thrv[2][2];
#pragma unroll
            for (int am = 0; am < 2; ++am)
#pragma unroll
                for (int h = 0; h < 2; ++h)
                    thrv[am][h] = sThr[warp_m * 32 + am * 16 + g + 8 * h];
#pragma unroll
            for (int am = 0; am < 2; ++am)
#pragma unroll
                for (int bn = 0; bn < 8; ++bn)
#pragma unroll
                    for (int e = 0; e < 4; ++e) {
                        int col = warp_n * 64 + bn * 8 + 2 * tq + (e & 1);
                        int h = e >> 1;
                        float s = __fsub_rn(En[col],
                                            __fmul_rn(2.0f, d[am][bn][e]));
                        runmin[am][h] = fminf(runmin[am][h], s);
                        if (s <= thrv[am][h]) {
                            int row = rowBase + warp_m * 32 + am * 16 + g + 8 * h;
                            int k = kChunk + t * N_TILE + col;
                            int ix = atomicAdd(&g_cnt[row], 1);
                            if (ix < CAP) g_cand[(size_t)row * CAP + ix] = k;
                        }
                    }
        }
        __syncthreads();
    }

    // both passes: write back per-row mins (seed / tighten for later waves)
#pragma unroll
    for (int am = 0; am < 2; ++am)
#pragma unroll
        for (int h = 0; h < 2; ++h) {
            float v = runmin[am][h];
            v = fminf(v, __shfl_xor_sync(0xFFFFFFFFu, v, 1));
            v = fminf(v, __shfl_xor_sync(0xFFFFFFFFu, v, 2));
            if (tq == 0)
                sMin[(warp_m * 32 + am * 16 + g + 8 * h) * 2 + warp_n] = v;
        }
    __syncthreads();
    if (tid < M_TILE) {
        float v = fminf(sMin[tid * 2], sMin[tid * 2 + 1]);
        atomicMin(&g_smin[rowBase + tid], f2o(v));
    }
}

// ---------------------------------------------------------------------------
// Rescore exactly (R8 VERBATIM — proven).
// ---------------------------------------------------------------------------
__global__ void vq_rescore_finalize(const float* __restrict__ z,
                                    const float* __restrict__ emb,
                                    float* __restrict__ out, int out_size) {
    __shared__ float sZ[2][C_DIM];
    __shared__ u64 sBest[8];
    __shared__ u64 sFinal[2];
    int tid = threadIdx.x, lane = tid & 31, w = tid >> 5;
    int rowBlk = blockIdx.x * 2;
    if (tid < 2 * C_DIM)
        sZ[tid >> 6][tid & 63] = z[(size_t)(rowBlk + (tid >> 6)) * C_DIM + (tid & 63)];
    __syncthreads();

    int wr = w >> 2, wi = w & 3;
    int row = rowBlk + wr;
    float znorm = g_znorm[row];
    int cnt = g_cnt[row];
    const float* zr = sZ[wr];
    u64 best = 0xFFFFFFFFFFFFFFFFull;

    if (cnt <= CAP) {
        for (int i = wi * 32 + lane; i < cnt; i += 128) {
            int k = g_cand[(size_t)row * CAP + i];
            const float* e = emb + (size_t)k * C_DIM;
            float dot = 0.f;
#pragma unroll
            for (int c = 0; c < C_DIM; ++c) dot = fmaf(zr[c], e[c], dot);
            float d2 = __fadd_rn(__fsub_rn(znorm, __fmul_rn(2.0f, dot)), g_enorm[k]);
            u64 p = ((u64)f2o(d2) << 32) | (u32)k;
            best = p < best ? p : best;
        }
    } else {  // overflow fallback: exact full scan (correctness net)
        for (int k = wi * 32 + lane; k < K_CODES; k += 128) {
            const float* e = emb + (size_t)k * C_DIM;
            float dot = 0.f;
#pragma unroll
            for (int c = 0; c < C_DIM; ++c) dot = fmaf(zr[c], e[c], dot);
            float d2 = __fadd_rn(__fsub_rn(znorm, __fmul_rn(2.0f, dot)), g_enorm[k]);
            u64 p = ((u64)f2o(d2) << 32) | (u32)k;
            best = p < best ? p : best;
        }
    }
#pragma unroll
    for (int st = 16; st >= 1; st >>= 1) {
        u64 o = __shfl_xor_sync(0xFFFFFFFFu, best, st);
        best = o < best ? o : best;
    }
    if (lane == 0) sBest[w] = best;
    __syncthreads();
    if (tid < 2) {
        u64 m = sBest[tid * 4];
#pragma unroll
        for (int q = 1; q < 4; ++q) m = sBest[tid * 4 + q] < m ? sBest[tid * 4 + q] : m;
        sFinal[tid] = m;
    }
    __syncthreads();

    if (wi == 0) {
        u32 idx = (u32)sFinal[wr];
        double part = 0.0;
#pragma unroll
        for (int q = 0; q < 2; ++q) {
            int c = lane + 32 * q;
            float e = emb[(size_t)idx * C_DIM + c];
            float zv = zr[c];
            if ((size_t)row * C_DIM + c < (size_t)out_size)
                out[(size_t)row * C_DIM + c] = __fadd_rn(zv, __fsub_rn(e, zv));
            float s = __fsub_rn(zv, e);
            part += (double)__fmul_rn(s, s);
        }
#pragma unroll
        for (int st = 16; st >= 1; st >>= 1)
            part += __shfl_xor_sync(0xFFFFFFFFu, part, st);
        if (lane == 0) {
            g_rowloss[row] = part;
            if (out_size >= 133122) out[131074 + row] = (float)idx;
        }
    }
}

__global__ void vq_loss(float* __restrict__ out, int out_size) {
    __shared__ double sD[256];
    int tid = threadIdx.x;
    double v[8];
#pragma unroll
    for (int q = 0; q < 8; ++q) v[q] = g_rowloss[tid + 256 * q];
    double s = 0.0;
#pragma unroll
    for (int q = 0; q < 8; ++q) s += v[q];
    sD[tid] = s;
    __syncthreads();
#pragma unroll
    for (int st = 128; st >= 1; st >>= 1) {
        if (tid < st) sD[tid] += sD[tid + st];
        __syncthreads();
    }
    if (tid == 0 && out_size >= 133122) {
        float m = (float)(sD[0] / 131072.0);
        out[131072] = m;
        out[131073] = m;
    }
}

// ---------------------------------------------------------------------------
extern "C" void kernel_launch(void* const* d_in, const int* in_sizes, int n_in,
                              void* d_out, int out_size) {
    const float* z = (const float*)d_in[0];
    const float* emb = (const float*)d_in[1];
    if (n_in >= 2 && in_sizes[0] == K_CODES * C_DIM && in_sizes[1] == N_ROWS * C_DIM) {
        const float* t = z; z = emb; emb = t;
    }
    float* out = (float*)d_out;

    cudaFuncSetAttribute(vq_mma_pass,
                         cudaFuncAttributeMaxDynamicSharedMemorySize, 57344);

    vq_prep<<<(K_CODES + N_ROWS) / 256, 256>>>(z, emb);
    // GEMM-seed: pass 0 on a 16-chunk sub-grid (~one wave, codes 0..16383)
    vq_mma_pass<<<dim3(NCHUNKS_SEED, N_ROWS / M_TILE), 256, 57344>>>(0);
    // Single collection pass, per-tile monotone threshold refresh
    vq_mma_pass<<<dim3(NCHUNKS, N_ROWS / M_TILE), 256, 57344>>>(1);
    vq_rescore_finalize<<<N_ROWS / 2, 256>>>(z, emb, out, out_size);
    vq_loss<<<1, 256>>>(out, out_size);
}

// round 14
// speedup vs baseline: 1.0922x; 1.0839x over previous
#include <cuda_runtime.h>
#include <cuda_bf16.h>

typedef unsigned int u32;
typedef unsigned long long u64;

#define N_ROWS 2048
#define K_CODES 81920
#define C_DIM 64
#define M_TILE 128
#define N_TILE 128
#define CHUNK 1024
#define TILES (CHUNK / N_TILE)     // 8
#define NCHUNKS (K_CODES / CHUNK)  // 80
#define NCHUNKS_SEED 16            // seed pass: codes 0..16383, ~one wave
#define PITCHB 144                 // bytes per smem row (72 bf16, conflict-free)
#define CAP 2048

// ---------------- device scratch (no allocation allowed) -------------------
__device__ __nv_bfloat16 g_zbf[N_ROWS * C_DIM];
__device__ __nv_bfloat16 g_ebf[K_CODES * C_DIM];
__device__ float g_enorm[K_CODES];
__device__ float g_znorm[N_ROWS];
__device__ float g_sumabs[N_ROWS];
__device__ u32 g_smin[N_ROWS];     // orderable-uint float (monotone decreasing)
__device__ u32 g_emax;             // bits of max|emb|
__device__ int g_cnt[N_ROWS];
__device__ int g_cand[N_ROWS * CAP];
__device__ double g_rowloss[N_ROWS];

// ---------------- helpers ---------------------------------------------------
__device__ __forceinline__ u32 f2o(float f) {
    u32 b = __float_as_uint(f);
    return (b & 0x80000000u) ? ~b : (b | 0x80000000u);
}
__device__ __forceinline__ float o2f(u32 o) {
    u32 b = (o & 0x80000000u) ? (o ^ 0x80000000u) : ~o;
    return __uint_as_float(b);
}
__device__ __forceinline__ u32 smem_u32(const void* p) {
    u32 a; asm("{ .reg .u64 t; cvta.to.shared.u64 t, %1; cvt.u32.u64 %0, t; }"
               : "=r"(a) : "l"(p));
    return a;
}
__device__ __forceinline__ void cpa16(u32 dst, const void* src) {
    asm volatile("cp.async.cg.shared.global [%0], [%1], 16;" :: "r"(dst), "l"(src));
}
__device__ __forceinline__ void cpa_commit() { asm volatile("cp.async.commit_group;"); }
template <int N> __device__ __forceinline__ void cpa_wait() {
    asm volatile("cp.async.wait_group %0;" :: "n"(N));
}
__device__ __forceinline__ void ldsm4(u32* r, u32 addr) {
    asm volatile("ldmatrix.sync.aligned.m8n8.x4.shared.b16 {%0,%1,%2,%3}, [%4];"
                 : "=r"(r[0]), "=r"(r[1]), "=r"(r[2]), "=r"(r[3]) : "r"(addr));
}
__device__ __forceinline__ void mma16816(float* d, const u32* a, u32 b0, u32 b1) {
    asm volatile(
        "mma.sync.aligned.m16n8k16.row.col.f32.bf16.bf16.f32 "
        "{%0,%1,%2,%3},{%4,%5,%6,%7},{%8,%9},{%0,%1,%2,%3};"
        : "+f"(d[0]), "+f"(d[1]), "+f"(d[2]), "+f"(d[3])
        : "r"(a[0]), "r"(a[1]), "r"(a[2]), "r"(a[3]), "r"(b0), "r"(b1));
}

// ---------------------------------------------------------------------------
// Prep — R8 VERBATIM (proven-fast configuration).
// ---------------------------------------------------------------------------
__global__ void vq_prep(const float* __restrict__ z, const float* __restrict__ emb) {
    __shared__ float sMax[256];
    int tid = threadIdx.x;
    int t = blockIdx.x * 256 + tid;
    float lmax = 0.f;
    if (t < K_CODES) {
        const float* e = emb + (size_t)t * C_DIM;
        float s = 0.f;
#pragma unroll
        for (int c = 0; c < C_DIM; ++c) {
            float v = e[c];
            s = fmaf(v, v, s);
            lmax = fmaxf(lmax, fabsf(v));
            g_ebf[(size_t)t * C_DIM + c] = __float2bfloat16_rn(v);
        }
        g_enorm[t] = s;
    } else if (t < K_CODES + N_ROWS) {
        int r = t - K_CODES;
        const float* zr = z + (size_t)r * C_DIM;
        float s = 0.f, sa = 0.f;
#pragma unroll
        for (int c = 0; c < C_DIM; ++c) {
            float v = zr[c];
            s = fmaf(v, v, s);
            sa += fabsf(v);
            g_zbf[(size_t)r * C_DIM + c] = __float2bfloat16_rn(v);
        }
        g_znorm[r] = s;
        g_sumabs[r] = sa;
        g_smin[r] = 0xFFFFFFFFu;
        g_cnt[r] = 0;
    }
    sMax[tid] = lmax;
    __syncthreads();
#pragma unroll
    for (int st = 128; st >= 1; st >>= 1) {
        if (tid < st) sMax[tid] = fmaxf(sMax[tid], sMax[tid + st]);
        __syncthreads();
    }
    if (tid == 0 && sMax[0] > 0.f) atomicMax(&g_emax, __float_as_uint(sMax[0]));
}

// ---------------------------------------------------------------------------
// bf16 HMMA filter — R13 kernel with TRANSPOSED grid axes:
//   rowBase = blockIdx.x (16 values), kChunk = blockIdx.y (chunk-major waves).
// Wave w of the collection pass covers chunks [~18w, ~18(w+1)) for ALL rows,
// so every row's threshold tightens monotonically across waves via the
// end-of-CTA atomicMin + per-tile refresh. Soundness: any g_smin snapshot
// >= true min -> superset collected -> exact rescore identical.
// ---------------------------------------------------------------------------
__global__ __launch_bounds__(256, 2) void vq_mma_pass(int pass) {
    extern __shared__ char smem[];
    const u32 sbase = smem_u32(smem);
    // offsets: A 0..18432, B0 18432, B1 36864, En0 55296, En1 55808,
    //          sMar 56320 (512B), sThr 56832 (512B); sMin reuses 56320 post-loop
    float* sMar = (float*)(smem + 56320);
    float* sThr = (float*)(smem + 56832);
    float* sMin = (float*)(smem + 56320);

    const int tid = threadIdx.x, lane = tid & 31, wid = tid >> 5;
    const int warp_m = wid >> 1, warp_n = wid & 1;
    const int g = lane >> 2, tq = lane & 3;
    const int rowBase = blockIdx.x * M_TILE;   // TRANSPOSED
    const int kChunk = blockIdx.y * CHUNK;     // TRANSPOSED

    // group 0: A tile + B tile 0 + En0
#pragma unroll
    for (int j = 0; j < 4; ++j) {
        int idx = tid + 256 * j, r = idx >> 3, sg = idx & 7;
        cpa16(sbase + r * PITCHB + sg * 16,
              g_zbf + (size_t)(rowBase + r) * C_DIM + sg * 8);
        cpa16(sbase + 18432 + r * PITCHB + sg * 16,
              g_ebf + (size_t)(kChunk + r) * C_DIM + sg * 8);
    }
    if (tid < 32) cpa16(sbase + 55296 + tid * 16, g_enorm + kChunk + tid * 4);
    cpa_commit();

    // per-row margins into smem (pass 1 only); same tid later composes sThr
    if (pass && tid < M_TILE) {
        int r = rowBase + tid;
        sMar[tid] = 4.0f * 0.0082f * __uint_as_float(g_emax) * g_sumabs[r]
                  + g_znorm[r] * 9.5367431640625e-07f + 2e-6f;
    }

    float runmin[2][2];
#pragma unroll
    for (int am = 0; am < 2; ++am)
#pragma unroll
        for (int h = 0; h < 2; ++h) runmin[am][h] = __int_as_float(0x7F800000);

    // ldmatrix lane base addresses (R5/R11-proven mapping)
    u32 aoff[2];
#pragma unroll
    for (int am = 0; am < 2; ++am)
        aoff[am] = sbase + (u32)(warp_m * 32 + am * 16 + (lane & 15)) * PITCHB
                 + ((lane >> 4) & 1) * 16;
    const u32 boffl = (u32)(warp_n * 64 + ((lane >> 4) << 3) + (lane & 7)) * PITCHB
                    + ((lane >> 3) & 1) * 16;

    for (int t = 0; t < TILES; ++t) {
        int buf = t & 1;
        if (t + 1 < TILES) {
            u32 db = sbase + (((t + 1) & 1) ? 36864u : 18432u);
            const __nv_bfloat16* src =
                g_ebf + (size_t)(kChunk + (t + 1) * N_TILE) * C_DIM;
#pragma unroll
            for (int j = 0; j < 4; ++j) {
                int idx = tid + 256 * j, r = idx >> 3, sg = idx & 7;
                cpa16(db + r * PITCHB + sg * 16, src + (size_t)r * C_DIM + sg * 8);
            }
            if (tid < 32)
                cpa16(sbase + (((t + 1) & 1) ? 55808u : 55296u) + tid * 16,
                      g_enorm + kChunk + (t + 1) * N_TILE + tid * 4);
            cpa_commit();
            cpa_wait<1>();
        } else {
            cpa_wait<0>();
        }

        // per-tile threshold refresh (stale smin only enlarges thr -> sound)
        if (pass && tid < M_TILE)
            sThr[tid] = o2f(__ldcg(&g_smin[rowBase + tid])) + sMar[tid];
        __syncthreads();

        const u32 Bb = sbase + (buf ? 36864u : 18432u);
        const float* En = (const float*)(smem + (buf ? 55808 : 55296));

        float d[2][8][4];
#pragma unroll
        for (int am = 0; am < 2; ++am)
#pragma unroll
            for (int bn = 0; bn < 8; ++bn)
#pragma unroll
                for (int e = 0; e < 4; ++e) d[am][bn][e] = 0.f;

#pragma unroll
        for (int ks = 0; ks < 4; ++ks) {
            u32 aa[2][4];
            ldsm4(aa[0], aoff[0] + ks * 32);
            ldsm4(aa[1], aoff[1] + ks * 32);
#pragma unroll
            for (int bp = 0; bp < 4; ++bp) {
                u32 bb[4];
                ldsm4(bb, Bb + boffl + bp * (16 * PITCHB) + ks * 32);
                mma16816(d[0][2 * bp],     aa[0], bb[0], bb[1]);
                mma16816(d[0][2 * bp + 1], aa[0], bb[2], bb[3]);
                mma16816(d[1][2 * bp],     aa[1], bb[0], bb[1]);
                mma16816(d[1][2 * bp + 1], aa[1], bb[2], bb[3]);
            }
        }

        if (!pass) {
            // seed pass: running min only
#pragma unroll
            for (int am = 0; am < 2; ++am)
#pragma unroll
                for (int bn = 0; bn < 8; ++bn)
#pragma unroll
                    for (int e = 0; e < 4; ++e) {
                        int col = warp_n * 64 + bn * 8 + 2 * tq + (e & 1);
                        float s = __fsub_rn(En[col],
                                            __fmul_rn(2.0f, d[am][bn][e]));
                        runmin[am][e >> 1] = fminf(runmin[am][e >> 1], s);
                    }
        } else {
            // collection pass: thresholds from smem (short-lived regs only)
            float thrv[2][2];
#pragma unroll
            for (int am = 0; am < 2; ++am)
#pragma unroll
                for (int h = 0; h < 2; ++h)
                    thrv[am][h] = sThr[warp_m * 32 + am * 16 + g + 8 * h];
#pragma unroll
            for (int am = 0; am < 2; ++am)
#pragma unroll
                for (int bn = 0; bn < 8; ++bn)
#pragma unroll
                    for (int e = 0; e < 4; ++e) {
                        int col = warp_n * 64 + bn * 8 + 2 * tq + (e & 1);
                        int h = e >> 1;
                        float s = __fsub_rn(En[col],
                                            __fmul_rn(2.0f, d[am][bn][e]));
                        runmin[am][h] = fminf(runmin[am][h], s);
                        if (s <= thrv[am][h]) {
                            int row = rowBase + warp_m * 32 + am * 16 + g + 8 * h;
                            int k = kChunk + t * N_TILE + col;
                            int ix = atomicAdd(&g_cnt[row], 1);
                            if (ix < CAP) g_cand[(size_t)row * CAP + ix] = k;
                        }
                    }
        }
        __syncthreads();
    }

    // both passes: write back per-row mins (seed / tighten for later waves)
#pragma unroll
    for (int am = 0; am < 2; ++am)
#pragma unroll
        for (int h = 0; h < 2; ++h) {
            float v = runmin[am][h];
            v = fminf(v, __shfl_xor_sync(0xFFFFFFFFu, v, 1));
            v = fminf(v, __shfl_xor_sync(0xFFFFFFFFu, v, 2));
            if (tq == 0)
                sMin[(warp_m * 32 + am * 16 + g + 8 * h) * 2 + warp_n] = v;
        }
    __syncthreads();
    if (tid < M_TILE) {
        float v = fminf(sMin[tid * 2], sMin[tid * 2 + 1]);
        atomicMin(&g_smin[rowBase + tid], f2o(v));
    }
}

// ---------------------------------------------------------------------------
// Rescore exactly (R8 VERBATIM — proven).
// ---------------------------------------------------------------------------
__global__ void vq_rescore_finalize(const float* __restrict__ z,
                                    const float* __restrict__ emb,
                                    float* __restrict__ out, int out_size) {
    __shared__ float sZ[2][C_DIM];
    __shared__ u64 sBest[8];
    __shared__ u64 sFinal[2];
    int tid = threadIdx.x, lane = tid & 31, w = tid >> 5;
    int rowBlk = blockIdx.x * 2;
    if (tid < 2 * C_DIM)
        sZ[tid >> 6][tid & 63] = z[(size_t)(rowBlk + (tid >> 6)) * C_DIM + (tid & 63)];
    __syncthreads();

    int wr = w >> 2, wi = w & 3;
    int row = rowBlk + wr;
    float znorm = g_znorm[row];
    int cnt = g_cnt[row];
    const float* zr = sZ[wr];
    u64 best = 0xFFFFFFFFFFFFFFFFull;

    if (cnt <= CAP) {
        for (int i = wi * 32 + lane; i < cnt; i += 128) {
            int k = g_cand[(size_t)row * CAP + i];
            const float* e = emb + (size_t)k * C_DIM;
            float dot = 0.f;
#pragma unroll
            for (int c = 0; c < C_DIM; ++c) dot = fmaf(zr[c], e[c], dot);
            float d2 = __fadd_rn(__fsub_rn(znorm, __fmul_rn(2.0f, dot)), g_enorm[k]);
            u64 p = ((u64)f2o(d2) << 32) | (u32)k;
            best = p < best ? p : best;
        }
    } else {  // overflow fallback: exact full scan (correctness net)
        for (int k = wi * 32 + lane; k < K_CODES; k += 128) {
            const float* e = emb + (size_t)k * C_DIM;
            float dot = 0.f;
#pragma unroll
            for (int c = 0; c < C_DIM; ++c) dot = fmaf(zr[c], e[c], dot);
            float d2 = __fadd_rn(__fsub_rn(znorm, __fmul_rn(2.0f, dot)), g_enorm[k]);
            u64 p = ((u64)f2o(d2) << 32) | (u32)k;
            best = p < best ? p : best;
        }
    }
#pragma unroll
    for (int st = 16; st >= 1; st >>= 1) {
        u64 o = __shfl_xor_sync(0xFFFFFFFFu, best, st);
        best = o < best ? o : best;
    }
    if (lane == 0) sBest[w] = best;
    __syncthreads();
    if (tid < 2) {
        u64 m = sBest[tid * 4];
#pragma unroll
        for (int q = 1; q < 4; ++q) m = sBest[tid * 4 + q] < m ? sBest[tid * 4 + q] : m;
        sFinal[tid] = m;
    }
    __syncthreads();

    if (wi == 0) {
        u32 idx = (u32)sFinal[wr];
        double part = 0.0;
#pragma unroll
        for (int q = 0; q < 2; ++q) {
            int c = lane + 32 * q;
            float e = emb[(size_t)idx * C_DIM + c];
            float zv = zr[c];
            if ((size_t)row * C_DIM + c < (size_t)out_size)
                out[(size_t)row * C_DIM + c] = __fadd_rn(zv, __fsub_rn(e, zv));
            float s = __fsub_rn(zv, e);
            part += (double)__fmul_rn(s, s);
        }
#pragma unroll
        for (int st = 16; st >= 1; st >>= 1)
            part += __shfl_xor_sync(0xFFFFFFFFu, part, st);
        if (lane == 0) {
            g_rowloss[row] = part;
            if (out_size >= 133122) out[131074 + row] = (float)idx;
        }
    }
}

__global__ void vq_loss(float* __restrict__ out, int out_size) {
    __shared__ double sD[256];
    int tid = threadIdx.x;
    double v[8];
#pragma unroll
    for (int q = 0; q < 8; ++q) v[q] = g_rowloss[tid + 256 * q];
    double s = 0.0;
#pragma unroll
    for (int q = 0; q < 8; ++q) s += v[q];
    sD[tid] = s;
    __syncthreads();
#pragma unroll
    for (int st = 128; st >= 1; st >>= 1) {
        if (tid < st) sD[tid] += sD[tid + st];
        __syncthreads();
    }
    if (tid == 0 && out_size >= 133122) {
        float m = (float)(sD[0] / 131072.0);
        out[131072] = m;
        out[131073] = m;
    }
}

// ---------------------------------------------------------------------------
extern "C" void kernel_launch(void* const* d_in, const int* in_sizes, int n_in,
                              void* d_out, int out_size) {
    const float* z = (const float*)d_in[0];
    const float* emb = (const float*)d_in[1];
    if (n_in >= 2 && in_sizes[0] == K_CODES * C_DIM && in_sizes[1] == N_ROWS * C_DIM) {
        const float* t = z; z = emb; emb = t;
    }
    float* out = (float*)d_out;

    cudaFuncSetAttribute(vq_mma_pass,
                         cudaFuncAttributeMaxDynamicSharedMemorySize, 57344);

    vq_prep<<<(K_CODES + N_ROWS) / 256, 256>>>(z, emb);
    // GEMM-seed: pass 0 on codes 0..16383 (grid: 16 row-groups x 16 chunks)
    vq_mma_pass<<<dim3(N_ROWS / M_TILE, NCHUNKS_SEED), 256, 57344>>>(0);
    // Single collection pass, chunk-major waves -> monotone tightening works
    vq_mma_pass<<<dim3(N_ROWS / M_TILE, NCHUNKS), 256, 57344>>>(1);
    vq_rescore_finalize<<<N_ROWS / 2, 256>>>(z, emb, out, out_size);
    vq_loss<<<1, 256>>>(out, out_size);
}

// round 15
// speedup vs baseline: 1.4596x; 1.3364x over previous
#include <cuda_runtime.h>
#include <cuda_bf16.h>

typedef unsigned int u32;
typedef unsigned long long u64;

#define N_ROWS 2048
#define K_CODES 81920
#define C_DIM 64
#define M_TILE 128
#define N_TILE 128
#define CHUNK 1024
#define TILES (CHUNK / N_TILE)     // 8
#define NCHUNKS (K_CODES / CHUNK)  // 80
#define NCHUNKS_SEED 16            // seed pass: codes 0..16383, ~one wave
#define PITCHB 144                 // bytes per smem row (72 bf16, conflict-free)
#define CAP 2048
#define PREP_ROWS 128              // rows per prep block
#define PREP_PITCH 68              // padded floats per smem row

// ---------------- device scratch (no allocation allowed) -------------------
__device__ __nv_bfloat16 g_zbf[N_ROWS * C_DIM];
__device__ __nv_bfloat16 g_ebf[K_CODES * C_DIM];
__device__ float g_enorm[K_CODES];
__device__ float g_znorm[N_ROWS];
__device__ float g_sumabs[N_ROWS];
__device__ u32 g_smin[N_ROWS];     // orderable-uint float (monotone decreasing)
__device__ u32 g_emax;             // bits of max|emb|
__device__ int g_cnt[N_ROWS];
__device__ int g_cand[N_ROWS * CAP];
__device__ double g_rowloss[N_ROWS];

// ---------------- helpers ---------------------------------------------------
__device__ __forceinline__ u32 f2o(float f) {
    u32 b = __float_as_uint(f);
    return (b & 0x80000000u) ? ~b : (b | 0x80000000u);
}
__device__ __forceinline__ float o2f(u32 o) {
    u32 b = (o & 0x80000000u) ? (o ^ 0x80000000u) : ~o;
    return __uint_as_float(b);
}
__device__ __forceinline__ u32 smem_u32(const void* p) {
    u32 a; asm("{ .reg .u64 t; cvta.to.shared.u64 t, %1; cvt.u32.u64 %0, t; }"
               : "=r"(a) : "l"(p));
    return a;
}
__device__ __forceinline__ void cpa16(u32 dst, const void* src) {
    asm volatile("cp.async.cg.shared.global [%0], [%1], 16;" :: "r"(dst), "l"(src));
}
__device__ __forceinline__ void cpa_commit() { asm volatile("cp.async.commit_group;"); }
template <int N> __device__ __forceinline__ void cpa_wait() {
    asm volatile("cp.async.wait_group %0;" :: "n"(N));
}
__device__ __forceinline__ void ldsm4(u32* r, u32 addr) {
    asm volatile("ldmatrix.sync.aligned.m8n8.x4.shared.b16 {%0,%1,%2,%3}, [%4];"
                 : "=r"(r[0]), "=r"(r[1]), "=r"(r[2]), "=r"(r[3]) : "r"(addr));
}
__device__ __forceinline__ void mma16816(float* d, const u32* a, u32 b0, u32 b1) {
    asm volatile(
        "mma.sync.aligned.m16n8k16.row.col.f32.bf16.bf16.f32 "
        "{%0,%1,%2,%3},{%4,%5,%6,%7},{%8,%9},{%0,%1,%2,%3};"
        : "+f"(d[0]), "+f"(d[1]), "+f"(d[2]), "+f"(d[3])
        : "r"(a[0]), "r"(a[1]), "r"(a[2]), "r"(a[3]), "r"(b0), "r"(b1));
}

// ---------------------------------------------------------------------------
// Prep v3 — coalesced, smem-staged. Norm math is BIT-IDENTICAL to R8 prep:
// per-row sequential fmaf over c=0..63 (same order), bf16 RN conversions.
// Blocks 0..639 handle emb rows, 640..655 handle z rows.
// ---------------------------------------------------------------------------
__global__ __launch_bounds__(256) void vq_prep(const float* __restrict__ z,
                                               const float* __restrict__ emb) {
    __shared__ float sZ[PREP_ROWS * PREP_PITCH];   // 34816 B, padded
    __shared__ float sMax[256];
    const int tid = threadIdx.x;
    const bool isE = blockIdx.x < (K_CODES / PREP_ROWS);
    const int rowBase = isE ? blockIdx.x * PREP_ROWS
                            : (blockIdx.x - K_CODES / PREP_ROWS) * PREP_ROWS;
    const float* src = isE ? emb : z;

    // stage 1: coalesced float4 loads -> padded smem; track |max| for emb
    float lmax = 0.f;
#pragma unroll
    for (int j = 0; j < 8; ++j) {
        int f = tid + 256 * j;             // float4 index within block tile
        int r = f >> 4, c4 = f & 15;
        float4 v = *reinterpret_cast<const float4*>(
            src + (size_t)(rowBase + r) * C_DIM + c4 * 4);
        sZ[r * PREP_PITCH + c4 * 4 + 0] = v.x;
        sZ[r * PREP_PITCH + c4 * 4 + 1] = v.y;
        sZ[r * PREP_PITCH + c4 * 4 + 2] = v.z;
        sZ[r * PREP_PITCH + c4 * 4 + 3] = v.w;
        if (isE)
            lmax = fmaxf(lmax, fmaxf(fmaxf(fabsf(v.x), fabsf(v.y)),
                                     fmaxf(fabsf(v.z), fabsf(v.w))));
    }
    __syncthreads();

    // stage 2: per-row norms, sequential fmaf order c=0..63 (bit-identical)
    if (tid < PREP_ROWS) {
        const float* row = sZ + tid * PREP_PITCH;
        if (isE) {
            float s = 0.f;
#pragma unroll
            for (int c = 0; c < C_DIM; ++c) {
                float v = row[c];
                s = fmaf(v, v, s);
            }
            g_enorm[rowBase + tid] = s;
        } else {
            float s = 0.f, sa = 0.f;
#pragma unroll
            for (int c = 0; c < C_DIM; ++c) {
                float v = row[c];
                s = fmaf(v, v, s);
                sa += fabsf(v);
            }
            g_znorm[rowBase + tid] = s;
            g_sumabs[rowBase + tid] = sa;
            g_smin[rowBase + tid] = 0xFFFFFFFFu;
            g_cnt[rowBase + tid] = 0;
        }
    }

    // stage 3: bf16 conversion, coalesced u64 stores (4 floats -> 1 u64)
    u64* dst = isE ? reinterpret_cast<u64*>(g_ebf) + (size_t)rowBase * 16
                   : reinterpret_cast<u64*>(g_zbf) + (size_t)rowBase * 16;
#pragma unroll
    for (int j = 0; j < 8; ++j) {
        int f = tid + 256 * j;
        int r = f >> 4, c4 = f & 15;
        const float* p = sZ + r * PREP_PITCH + c4 * 4;
        __nv_bfloat162 p0 = {__float2bfloat16_rn(p[0]), __float2bfloat16_rn(p[1])};
        __nv_bfloat162 p1 = {__float2bfloat16_rn(p[2]), __float2bfloat16_rn(p[3])};
        u64 pk = ((u64)*reinterpret_cast<u32*>(&p1) << 32)
               | *reinterpret_cast<u32*>(&p0);
        dst[f] = pk;
    }

    // emax block-reduce + atomicMax (emb blocks only contribute nonzero)
    sMax[tid] = lmax;
    __syncthreads();
#pragma unroll
    for (int st = 128; st >= 1; st >>= 1) {
        if (tid < st) sMax[tid] = fmaxf(sMax[tid], sMax[tid + st]);
        __syncthreads();
    }
    if (tid == 0 && sMax[0] > 0.f) atomicMax(&g_emax, __float_as_uint(sMax[0]));
}

// ---------------------------------------------------------------------------
// bf16 HMMA filter — R14 VERBATIM (transposed grid, per-tile refresh).
// ---------------------------------------------------------------------------
__global__ __launch_bounds__(256, 2) void vq_mma_pass(int pass) {
    extern __shared__ char smem[];
    const u32 sbase = smem_u32(smem);
    float* sMar = (float*)(smem + 56320);
    float* sThr = (float*)(smem + 56832);
    float* sMin = (float*)(smem + 56320);

    const int tid = threadIdx.x, lane = tid & 31, wid = tid >> 5;
    const int warp_m = wid >> 1, warp_n = wid & 1;
    const int g = lane >> 2, tq = lane & 3;
    const int rowBase = blockIdx.x * M_TILE;
    const int kChunk = blockIdx.y * CHUNK;

#pragma unroll
    for (int j = 0; j < 4; ++j) {
        int idx = tid + 256 * j, r = idx >> 3, sg = idx & 7;
        cpa16(sbase + r * PITCHB + sg * 16,
              g_zbf + (size_t)(rowBase + r) * C_DIM + sg * 8);
        cpa16(sbase + 18432 + r * PITCHB + sg * 16,
              g_ebf + (size_t)(kChunk + r) * C_DIM + sg * 8);
    }
    if (tid < 32) cpa16(sbase + 55296 + tid * 16, g_enorm + kChunk + tid * 4);
    cpa_commit();

    if (pass && tid < M_TILE) {
        int r = rowBase + tid;
        sMar[tid] = 4.0f * 0.0082f * __uint_as_float(g_emax) * g_sumabs[r]
                  + g_znorm[r] * 9.5367431640625e-07f + 2e-6f;
    }

    float runmin[2][2];
#pragma unroll
    for (int am = 0; am < 2; ++am)
#pragma unroll
        for (int h = 0; h < 2; ++h) runmin[am][h] = __int_as_float(0x7F800000);

    u32 aoff[2];
#pragma unroll
    for (int am = 0; am < 2; ++am)
        aoff[am] = sbase + (u32)(warp_m * 32 + am * 16 + (lane & 15)) * PITCHB
                 + ((lane >> 4) & 1) * 16;
    const u32 boffl = (u32)(warp_n * 64 + ((lane >> 4) << 3) + (lane & 7)) * PITCHB
                    + ((lane >> 3) & 1) * 16;

    for (int t = 0; t < TILES; ++t) {
        int buf = t & 1;
        if (t + 1 < TILES) {
            u32 db = sbase + (((t + 1) & 1) ? 36864u : 18432u);
            const __nv_bfloat16* src =
                g_ebf + (size_t)(kChunk + (t + 1) * N_TILE) * C_DIM;
#pragma unroll
            for (int j = 0; j < 4; ++j) {
                int idx = tid + 256 * j, r = idx >> 3, sg = idx & 7;
                cpa16(db + r * PITCHB + sg * 16, src + (size_t)r * C_DIM + sg * 8);
            }
            if (tid < 32)
                cpa16(sbase + (((t + 1) & 1) ? 55808u : 55296u) + tid * 16,
                      g_enorm + kChunk + (t + 1) * N_TILE + tid * 4);
            cpa_commit();
            cpa_wait<1>();
        } else {
            cpa_wait<0>();
        }

        if (pass && tid < M_TILE)
            sThr[tid] = o2f(__ldcg(&g_smin[rowBase + tid])) + sMar[tid];
        __syncthreads();

        const u32 Bb = sbase + (buf ? 36864u : 18432u);
        const float* En = (const float*)(smem + (buf ? 55808 : 55296));

        float d[2][8][4];
#pragma unroll
        for (int am = 0; am < 2; ++am)
#pragma unroll
            for (int bn = 0; bn < 8; ++bn)
#pragma unroll
                for (int e = 0; e < 4; ++e) d[am][bn][e] = 0.f;

#pragma unroll
        for (int ks = 0; ks < 4; ++ks) {
            u32 aa[2][4];
            ldsm4(aa[0], aoff[0] + ks * 32);
            ldsm4(aa[1], aoff[1] + ks * 32);
#pragma unroll
            for (int bp = 0; bp < 4; ++bp) {
                u32 bb[4];
                ldsm4(bb, Bb + boffl + bp * (16 * PITCHB) + ks * 32);
                mma16816(d[0][2 * bp],     aa[0], bb[0], bb[1]);
                mma16816(d[0][2 * bp + 1], aa[0], bb[2], bb[3]);
                mma16816(d[1][2 * bp],     aa[1], bb[0], bb[1]);
                mma16816(d[1][2 * bp + 1], aa[1], bb[2], bb[3]);
            }
        }

        if (!pass) {
#pragma unroll
            for (int am = 0; am < 2; ++am)
#pragma unroll
                for (int bn = 0; bn < 8; ++bn)
#pragma unroll
                    for (int e = 0; e < 4; ++e) {
                        int col = warp_n * 64 + bn * 8 + 2 * tq + (e & 1);
                        float s = __fsub_rn(En[col],
                                            __fmul_rn(2.0f, d[am][bn][e]));
                        runmin[am][e >> 1] = fminf(runmin[am][e >> 1], s);
                    }
        } else {
            float thrv[2][2];
#pragma unroll
            for (int am = 0; am < 2; ++am)
#pragma unroll
                for (int h = 0; h < 2; ++h)
                    thrv[am][h] = sThr[warp_m * 32 + am * 16 + g + 8 * h];
#pragma unroll
            for (int am = 0; am < 2; ++am)
#pragma unroll
                for (int bn = 0; bn < 8; ++bn)
#pragma unroll
                    for (int e = 0; e < 4; ++e) {
                        int col = warp_n * 64 + bn * 8 + 2 * tq + (e & 1);
                        int h = e >> 1;
                        float s = __fsub_rn(En[col],
                                            __fmul_rn(2.0f, d[am][bn][e]));
                        runmin[am][h] = fminf(runmin[am][h], s);
                        if (s <= thrv[am][h]) {
                            int row = rowBase + warp_m * 32 + am * 16 + g + 8 * h;
                            int k = kChunk + t * N_TILE + col;
                            int ix = atomicAdd(&g_cnt[row], 1);
                            if (ix < CAP) g_cand[(size_t)row * CAP + ix] = k;
                        }
                    }
        }
        __syncthreads();
    }

#pragma unroll
    for (int am = 0; am < 2; ++am)
#pragma unroll
        for (int h = 0; h < 2; ++h) {
            float v = runmin[am][h];
            v = fminf(v, __shfl_xor_sync(0xFFFFFFFFu, v, 1));
            v = fminf(v, __shfl_xor_sync(0xFFFFFFFFu, v, 2));
            if (tq == 0)
                sMin[(warp_m * 32 + am * 16 + g + 8 * h) * 2 + warp_n] = v;
        }
    __syncthreads();
    if (tid < M_TILE) {
        float v = fminf(sMin[tid * 2], sMin[tid * 2 + 1]);
        atomicMin(&g_smin[rowBase + tid], f2o(v));
    }
}

// ---------------------------------------------------------------------------
// Rescore exactly (R8 VERBATIM — proven).
// ---------------------------------------------------------------------------
__global__ void vq_rescore_finalize(const float* __restrict__ z,
                                    const float* __restrict__ emb,
                                    float* __restrict__ out, int out_size) {
    __shared__ float sZ[2][C_DIM];
    __shared__ u64 sBest[8];
    __shared__ u64 sFinal[2];
    int tid = threadIdx.x, lane = tid & 31, w = tid >> 5;
    int rowBlk = blockIdx.x * 2;
    if (tid < 2 * C_DIM)
        sZ[tid >> 6][tid & 63] = z[(size_t)(rowBlk + (tid >> 6)) * C_DIM + (tid & 63)];
    __syncthreads();

    int wr = w >> 2, wi = w & 3;
    int row = rowBlk + wr;
    float znorm = g_znorm[row];
    int cnt = g_cnt[row];
    const float* zr = sZ[wr];
    u64 best = 0xFFFFFFFFFFFFFFFFull;

    if (cnt <= CAP) {
        for (int i = wi * 32 + lane; i < cnt; i += 128) {
            int k = g_cand[(size_t)row * CAP + i];
            const float* e = emb + (size_t)k * C_DIM;
            float dot = 0.f;
#pragma unroll
            for (int c = 0; c < C_DIM; ++c) dot = fmaf(zr[c], e[c], dot);
            float d2 = __fadd_rn(__fsub_rn(znorm, __fmul_rn(2.0f, dot)), g_enorm[k]);
            u64 p = ((u64)f2o(d2) << 32) | (u32)k;
            best = p < best ? p : best;
        }
    } else {
        for (int k = wi * 32 + lane; k < K_CODES; k += 128) {
            const float* e = emb + (size_t)k * C_DIM;
            float dot = 0.f;
#pragma unroll
            for (int c = 0; c < C_DIM; ++c) dot = fmaf(zr[c], e[c], dot);
            float d2 = __fadd_rn(__fsub_rn(znorm, __fmul_rn(2.0f, dot)), g_enorm[k]);
            u64 p = ((u64)f2o(d2) << 32) | (u32)k;
            best = p < best ? p : best;
        }
    }
#pragma unroll
    for (int st = 16; st >= 1; st >>= 1) {
        u64 o = __shfl_xor_sync(0xFFFFFFFFu, best, st);
        best = o < best ? o : best;
    }
    if (lane == 0) sBest[w] = best;
    __syncthreads();
    if (tid < 2) {
        u64 m = sBest[tid * 4];
#pragma unroll
        for (int q = 1; q < 4; ++q) m = sBest[tid * 4 + q] < m ? sBest[tid * 4 + q] : m;
        sFinal[tid] = m;
    }
    __syncthreads();

    if (wi == 0) {
        u32 idx = (u32)sFinal[wr];
        double part = 0.0;
#pragma unroll
        for (int q = 0; q < 2; ++q) {
            int c = lane + 32 * q;
            float e = emb[(size_t)idx * C_DIM + c];
            float zv = zr[c];
            if ((size_t)row * C_DIM + c < (size_t)out_size)
                out[(size_t)row * C_DIM + c] = __fadd_rn(zv, __fsub_rn(e, zv));
            float s = __fsub_rn(zv, e);
            part += (double)__fmul_rn(s, s);
        }
#pragma unroll
        for (int st = 16; st >= 1; st >>= 1)
            part += __shfl_xor_sync(0xFFFFFFFFu, part, st);
        if (lane == 0) {
            g_rowloss[row] = part;
            if (out_size >= 133122) out[131074 + row] = (float)idx;
        }
    }
}

__global__ void vq_loss(float* __restrict__ out, int out_size) {
    __shared__ double sD[256];
    int tid = threadIdx.x;
    double v[8];
#pragma unroll
    for (int q = 0; q < 8; ++q) v[q] = g_rowloss[tid + 256 * q];
    double s = 0.0;
#pragma unroll
    for (int q = 0; q < 8; ++q) s += v[q];
    sD[tid] = s;
    __syncthreads();
#pragma unroll
    for (int st = 128; st >= 1; st >>= 1) {
        if (tid < st) sD[tid] += sD[tid + st];
        __syncthreads();
    }
    if (tid == 0 && out_size >= 133122) {
        float m = (float)(sD[0] / 131072.0);
        out[131072] = m;
        out[131073] = m;
    }
}

// ---------------------------------------------------------------------------
extern "C" void kernel_launch(void* const* d_in, const int* in_sizes, int n_in,
                              void* d_out, int out_size) {
    const float* z = (const float*)d_in[0];
    const float* emb = (const float*)d_in[1];
    if (n_in >= 2 && in_sizes[0] == K_CODES * C_DIM && in_sizes[1] == N_ROWS * C_DIM) {
        const float* t = z; z = emb; emb = t;
    }
    float* out = (float*)d_out;

    cudaFuncSetAttribute(vq_mma_pass,
                         cudaFuncAttributeMaxDynamicSharedMemorySize, 57344);

    vq_prep<<<(K_CODES + N_ROWS) / PREP_ROWS, 256>>>(z, emb);
    vq_mma_pass<<<dim3(N_ROWS / M_TILE, NCHUNKS_SEED), 256, 57344>>>(0);
    vq_mma_pass<<<dim3(N_ROWS / M_TILE, NCHUNKS), 256, 57344>>>(1);
    vq_rescore_finalize<<<N_ROWS / 2, 256>>>(z, emb, out, out_size);
    vq_loss<<<1, 256>>>(out, out_size);
}

// round 16
// speedup vs baseline: 1.8162x; 1.2443x over previous
#include <cuda_runtime.h>
#include <cuda_bf16.h>

typedef unsigned int u32;
typedef unsigned long long u64;

#define N_ROWS 2048
#define K_CODES 81920
#define C_DIM 64
#define M_TILE 128
#define N_TILE 128
#define CHUNK 1024
#define TILES (CHUNK / N_TILE)     // 8
#define NCHUNKS (K_CODES / CHUNK)  // 80
#define NCHUNKS_SEED 18            // seed pass: codes 0..18431, one full wave
#define PITCHB 144                 // bytes per smem row (72 bf16, conflict-free)
#define CAP 4096
#define PREP_ROWS 128              // rows per prep block
#define PREP_PITCH 68              // padded floats per smem row

// ---------------- device scratch (no allocation allowed) -------------------
__device__ __nv_bfloat16 g_zbf[N_ROWS * C_DIM];
__device__ __nv_bfloat16 g_ebf[K_CODES * C_DIM];
__device__ float g_enorm[K_CODES];
__device__ float g_znorm[N_ROWS];
__device__ float g_sumabs[N_ROWS];
__device__ u32 g_smin[N_ROWS];     // orderable-uint float (monotone decreasing)
__device__ u32 g_emax;             // bits of max|emb|
__device__ int g_cnt[N_ROWS];
__device__ int g_cand[N_ROWS * CAP];
__device__ double g_rowloss[N_ROWS];

// ---------------- helpers ---------------------------------------------------
__device__ __forceinline__ u32 f2o(float f) {
    u32 b = __float_as_uint(f);
    return (b & 0x80000000u) ? ~b : (b | 0x80000000u);
}
__device__ __forceinline__ float o2f(u32 o) {
    u32 b = (o & 0x80000000u) ? (o ^ 0x80000000u) : ~o;
    return __uint_as_float(b);
}
__device__ __forceinline__ u32 smem_u32(const void* p) {
    u32 a; asm("{ .reg .u64 t; cvta.to.shared.u64 t, %1; cvt.u32.u64 %0, t; }"
               : "=r"(a) : "l"(p));
    return a;
}
__device__ __forceinline__ void cpa16(u32 dst, const void* src) {
    asm volatile("cp.async.cg.shared.global [%0], [%1], 16;" :: "r"(dst), "l"(src));
}
__device__ __forceinline__ void cpa_commit() { asm volatile("cp.async.commit_group;"); }
template <int N> __device__ __forceinline__ void cpa_wait() {
    asm volatile("cp.async.wait_group %0;" :: "n"(N));
}
__device__ __forceinline__ void ldsm4(u32* r, u32 addr) {
    asm volatile("ldmatrix.sync.aligned.m8n8.x4.shared.b16 {%0,%1,%2,%3}, [%4];"
                 : "=r"(r[0]), "=r"(r[1]), "=r"(r[2]), "=r"(r[3]) : "r"(addr));
}
__device__ __forceinline__ void mma16816(float* d, const u32* a, u32 b0, u32 b1) {
    asm volatile(
        "mma.sync.aligned.m16n8k16.row.col.f32.bf16.bf16.f32 "
        "{%0,%1,%2,%3},{%4,%5,%6,%7},{%8,%9},{%0,%1,%2,%3};"
        : "+f"(d[0]), "+f"(d[1]), "+f"(d[2]), "+f"(d[3])
        : "r"(a[0]), "r"(a[1]), "r"(a[2]), "r"(a[3]), "r"(b0), "r"(b1));
}

// ---------------------------------------------------------------------------
// Prep v3 — R15 VERBATIM (coalesced, smem-staged; norm math bit-identical).
// ---------------------------------------------------------------------------
__global__ __launch_bounds__(256) void vq_prep(const float* __restrict__ z,
                                               const float* __restrict__ emb) {
    __shared__ float sZ[PREP_ROWS * PREP_PITCH];
    __shared__ float sMax[256];
    const int tid = threadIdx.x;
    const bool isE = blockIdx.x < (K_CODES / PREP_ROWS);
    const int rowBase = isE ? blockIdx.x * PREP_ROWS
                            : (blockIdx.x - K_CODES / PREP_ROWS) * PREP_ROWS;
    const float* src = isE ? emb : z;

    float lmax = 0.f;
#pragma unroll
    for (int j = 0; j < 8; ++j) {
        int f = tid + 256 * j;
        int r = f >> 4, c4 = f & 15;
        float4 v = *reinterpret_cast<const float4*>(
            src + (size_t)(rowBase + r) * C_DIM + c4 * 4);
        sZ[r * PREP_PITCH + c4 * 4 + 0] = v.x;
        sZ[r * PREP_PITCH + c4 * 4 + 1] = v.y;
        sZ[r * PREP_PITCH + c4 * 4 + 2] = v.z;
        sZ[r * PREP_PITCH + c4 * 4 + 3] = v.w;
        if (isE)
            lmax = fmaxf(lmax, fmaxf(fmaxf(fabsf(v.x), fabsf(v.y)),
                                     fmaxf(fabsf(v.z), fabsf(v.w))));
    }
    __syncthreads();

    if (tid < PREP_ROWS) {
        const float* row = sZ + tid * PREP_PITCH;
        if (isE) {
            float s = 0.f;
#pragma unroll
            for (int c = 0; c < C_DIM; ++c) {
                float v = row[c];
                s = fmaf(v, v, s);
            }
            g_enorm[rowBase + tid] = s;
        } else {
            float s = 0.f, sa = 0.f;
#pragma unroll
            for (int c = 0; c < C_DIM; ++c) {
                float v = row[c];
                s = fmaf(v, v, s);
                sa += fabsf(v);
            }
            g_znorm[rowBase + tid] = s;
            g_sumabs[rowBase + tid] = sa;
            g_smin[rowBase + tid] = 0xFFFFFFFFu;
            g_cnt[rowBase + tid] = 0;
        }
    }

    u64* dst = isE ? reinterpret_cast<u64*>(g_ebf) + (size_t)rowBase * 16
                   : reinterpret_cast<u64*>(g_zbf) + (size_t)rowBase * 16;
#pragma unroll
    for (int j = 0; j < 8; ++j) {
        int f = tid + 256 * j;
        int r = f >> 4, c4 = f & 15;
        const float* p = sZ + r * PREP_PITCH + c4 * 4;
        __nv_bfloat162 p0 = {__float2bfloat16_rn(p[0]), __float2bfloat16_rn(p[1])};
        __nv_bfloat162 p1 = {__float2bfloat16_rn(p[2]), __float2bfloat16_rn(p[3])};
        u64 pk = ((u64)*reinterpret_cast<u32*>(&p1) << 32)
               | *reinterpret_cast<u32*>(&p0);
        dst[f] = pk;
    }

    sMax[tid] = lmax;
    __syncthreads();
#pragma unroll
    for (int st = 128; st >= 1; st >>= 1) {
        if (tid < st) sMax[tid] = fmaxf(sMax[tid], sMax[tid + st]);
        __syncthreads();
    }
    if (tid == 0 && sMax[0] > 0.f) atomicMax(&g_emax, __float_as_uint(sMax[0]));
}

// ---------------------------------------------------------------------------
// bf16 HMMA filter — R14/R15 VERBATIM except the margin's tie-bin term:
// znorm*2^-20 (8 ulps of d2) -> znorm*3.0e-7 (~2.5 ulps). RN rounding is
// monotone, so every possible rounded-tie winner lies within 1 ulp of the
// true min; 2.5 ulps + 2e-6 slack still strictly over-bounds the required
// candidate set while cutting the dominant margin term ~3x.
// ---------------------------------------------------------------------------
__global__ __launch_bounds__(256, 2) void vq_mma_pass(int pass) {
    extern __shared__ char smem[];
    const u32 sbase = smem_u32(smem);
    float* sMar = (float*)(smem + 56320);
    float* sThr = (float*)(smem + 56832);
    float* sMin = (float*)(smem + 56320);

    const int tid = threadIdx.x, lane = tid & 31, wid = tid >> 5;
    const int warp_m = wid >> 1, warp_n = wid & 1;
    const int g = lane >> 2, tq = lane & 3;
    const int rowBase = blockIdx.x * M_TILE;
    const int kChunk = blockIdx.y * CHUNK;

#pragma unroll
    for (int j = 0; j < 4; ++j) {
        int idx = tid + 256 * j, r = idx >> 3, sg = idx & 7;
        cpa16(sbase + r * PITCHB + sg * 16,
              g_zbf + (size_t)(rowBase + r) * C_DIM + sg * 8);
        cpa16(sbase + 18432 + r * PITCHB + sg * 16,
              g_ebf + (size_t)(kChunk + r) * C_DIM + sg * 8);
    }
    if (tid < 32) cpa16(sbase + 55296 + tid * 16, g_enorm + kChunk + tid * 4);
    cpa_commit();

    if (pass && tid < M_TILE) {
        int r = rowBase + tid;
        sMar[tid] = 4.0f * 0.0082f * __uint_as_float(g_emax) * g_sumabs[r]
                  + g_znorm[r] * 3.0e-7f + 2e-6f;
    }

    float runmin[2][2];
#pragma unroll
    for (int am = 0; am < 2; ++am)
#pragma unroll
        for (int h = 0; h < 2; ++h) runmin[am][h] = __int_as_float(0x7F800000);

    u32 aoff[2];
#pragma unroll
    for (int am = 0; am < 2; ++am)
        aoff[am] = sbase + (u32)(warp_m * 32 + am * 16 + (lane & 15)) * PITCHB
                 + ((lane >> 4) & 1) * 16;
    const u32 boffl = (u32)(warp_n * 64 + ((lane >> 4) << 3) + (lane & 7)) * PITCHB
                    + ((lane >> 3) & 1) * 16;

    for (int t = 0; t < TILES; ++t) {
        int buf = t & 1;
        if (t + 1 < TILES) {
            u32 db = sbase + (((t + 1) & 1) ? 36864u : 18432u);
            const __nv_bfloat16* src =
                g_ebf + (size_t)(kChunk + (t + 1) * N_TILE) * C_DIM;
#pragma unroll
            for (int j = 0; j < 4; ++j) {
                int idx = tid + 256 * j, r = idx >> 3, sg = idx & 7;
                cpa16(db + r * PITCHB + sg * 16, src + (size_t)r * C_DIM + sg * 8);
            }
            if (tid < 32)
                cpa16(sbase + (((t + 1) & 1) ? 55808u : 55296u) + tid * 16,
                      g_enorm + kChunk + (t + 1) * N_TILE + tid * 4);
            cpa_commit();
            cpa_wait<1>();
        } else {
            cpa_wait<0>();
        }

        if (pass && tid < M_TILE)
            sThr[tid] = o2f(__ldcg(&g_smin[rowBase + tid])) + sMar[tid];
        __syncthreads();

        const u32 Bb = sbase + (buf ? 36864u : 18432u);
        const float* En = (const float*)(smem + (buf ? 55808 : 55296));

        float d[2][8][4];
#pragma unroll
        for (int am = 0; am < 2; ++am)
#pragma unroll
            for (int bn = 0; bn < 8; ++bn)
#pragma unroll
                for (int e = 0; e < 4; ++e) d[am][bn][e] = 0.f;

#pragma unroll
        for (int ks = 0; ks < 4; ++ks) {
            u32 aa[2][4];
            ldsm4(aa[0], aoff[0] + ks * 32);
            ldsm4(aa[1], aoff[1] + ks * 32);
#pragma unroll
            for (int bp = 0; bp < 4; ++bp) {
                u32 bb[4];
                ldsm4(bb, Bb + boffl + bp * (16 * PITCHB) + ks * 32);
                mma16816(d[0][2 * bp],     aa[0], bb[0], bb[1]);
                mma16816(d[0][2 * bp + 1], aa[0], bb[2], bb[3]);
                mma16816(d[1][2 * bp],     aa[1], bb[0], bb[1]);
                mma16816(d[1][2 * bp + 1], aa[1], bb[2], bb[3]);
            }
        }

        if (!pass) {
#pragma unroll
            for (int am = 0; am < 2; ++am)
#pragma unroll
                for (int bn = 0; bn < 8; ++bn)
#pragma unroll
                    for (int e = 0; e < 4; ++e) {
                        int col = warp_n * 64 + bn * 8 + 2 * tq + (e & 1);
                        float s = __fsub_rn(En[col],
                                            __fmul_rn(2.0f, d[am][bn][e]));
                        runmin[am][e >> 1] = fminf(runmin[am][e >> 1], s);
                    }
        } else {
            float thrv[2][2];
#pragma unroll
            for (int am = 0; am < 2; ++am)
#pragma unroll
                for (int h = 0; h < 2; ++h)
                    thrv[am][h] = sThr[warp_m * 32 + am * 16 + g + 8 * h];
#pragma unroll
            for (int am = 0; am < 2; ++am)
#pragma unroll
                for (int bn = 0; bn < 8; ++bn)
#pragma unroll
                    for (int e = 0; e < 4; ++e) {
                        int col = warp_n * 64 + bn * 8 + 2 * tq + (e & 1);
                        int h = e >> 1;
                        float s = __fsub_rn(En[col],
                                            __fmul_rn(2.0f, d[am][bn][e]));
                        runmin[am][h] = fminf(runmin[am][h], s);
                        if (s <= thrv[am][h]) {
                            int row = rowBase + warp_m * 32 + am * 16 + g + 8 * h;
                            int k = kChunk + t * N_TILE + col;
                            int ix = atomicAdd(&g_cnt[row], 1);
                            if (ix < CAP) g_cand[(size_t)row * CAP + ix] = k;
                        }
                    }
        }
        __syncthreads();
    }

#pragma unroll
    for (int am = 0; am < 2; ++am)
#pragma unroll
        for (int h = 0; h < 2; ++h) {
            float v = runmin[am][h];
            v = fminf(v, __shfl_xor_sync(0xFFFFFFFFu, v, 1));
            v = fminf(v, __shfl_xor_sync(0xFFFFFFFFu, v, 2));
            if (tq == 0)
                sMin[(warp_m * 32 + am * 16 + g + 8 * h) * 2 + warp_n] = v;
        }
    __syncthreads();
    if (tid < M_TILE) {
        float v = fminf(sMin[tid * 2], sMin[tid * 2 + 1]);
        atomicMin(&g_smin[rowBase + tid], f2o(v));
    }
}

// ---------------------------------------------------------------------------
// Rescore exactly (R8 VERBATIM — proven).
// ---------------------------------------------------------------------------
__global__ void vq_rescore_finalize(const float* __restrict__ z,
                                    const float* __restrict__ emb,
                                    float* __restrict__ out, int out_size) {
    __shared__ float sZ[2][C_DIM];
    __shared__ u64 sBest[8];
    __shared__ u64 sFinal[2];
    int tid = threadIdx.x, lane = tid & 31, w = tid >> 5;
    int rowBlk = blockIdx.x * 2;
    if (tid < 2 * C_DIM)
        sZ[tid >> 6][tid & 63] = z[(size_t)(rowBlk + (tid >> 6)) * C_DIM + (tid & 63)];
    __syncthreads();

    int wr = w >> 2, wi = w & 3;
    int row = rowBlk + wr;
    float znorm = g_znorm[row];
    int cnt = g_cnt[row];
    const float* zr = sZ[wr];
    u64 best = 0xFFFFFFFFFFFFFFFFull;

    if (cnt <= CAP) {
        for (int i = wi * 32 + lane; i < cnt; i += 128) {
            int k = g_cand[(size_t)row * CAP + i];
            const float* e = emb + (size_t)k * C_DIM;
            float dot = 0.f;
#pragma unroll
            for (int c = 0; c < C_DIM; ++c) dot = fmaf(zr[c], e[c], dot);
            float d2 = __fadd_rn(__fsub_rn(znorm, __fmul_rn(2.0f, dot)), g_enorm[k]);
            u64 p = ((u64)f2o(d2) << 32) | (u32)k;
            best = p < best ? p : best;
        }
    } else {
        for (int k = wi * 32 + lane; k < K_CODES; k += 128) {
            const float* e = emb + (size_t)k * C_DIM;
            float dot = 0.f;
#pragma unroll
            for (int c = 0; c < C_DIM; ++c) dot = fmaf(zr[c], e[c], dot);
            float d2 = __fadd_rn(__fsub_rn(znorm, __fmul_rn(2.0f, dot)), g_enorm[k]);
            u64 p = ((u64)f2o(d2) << 32) | (u32)k;
            best = p < best ? p : best;
        }
    }
#pragma unroll
    for (int st = 16; st >= 1; st >>= 1) {
        u64 o = __shfl_xor_sync(0xFFFFFFFFu, best, st);
        best = o < best ? o : best;
    }
    if (lane == 0) sBest[w] = best;
    __syncthreads();
    if (tid < 2) {
        u64 m = sBest[tid * 4];
#pragma unroll
        for (int q = 1; q < 4; ++q) m = sBest[tid * 4 + q] < m ? sBest[tid * 4 + q] : m;
        sFinal[tid] = m;
    }
    __syncthreads();

    if (wi == 0) {
        u32 idx = (u32)sFinal[wr];
        double part = 0.0;
#pragma unroll
        for (int q = 0; q < 2; ++q) {
            int c = lane + 32 * q;
            float e = emb[(size_t)idx * C_DIM + c];
            float zv = zr[c];
            if ((size_t)row * C_DIM + c < (size_t)out_size)
                out[(size_t)row * C_DIM + c] = __fadd_rn(zv, __fsub_rn(e, zv));
            float s = __fsub_rn(zv, e);
            part += (double)__fmul_rn(s, s);
        }
#pragma unroll
        for (int st = 16; st >= 1; st >>= 1)
            part += __shfl_xor_sync(0xFFFFFFFFu, part, st);
        if (lane == 0) {
            g_rowloss[row] = part;
            if (out_size >= 133122) out[131074 + row] = (float)idx;
        }
    }
}

__global__ void vq_loss(float* __restrict__ out, int out_size) {
    __shared__ double sD[256];
    int tid = threadIdx.x;
    double v[8];
#pragma unroll
    for (int q = 0; q < 8; ++q) v[q] = g_rowloss[tid + 256 * q];
    double s = 0.0;
#pragma unroll
    for (int q = 0; q < 8; ++q) s += v[q];
    sD[tid] = s;
    __syncthreads();
#pragma unroll
    for (int st = 128; st >= 1; st >>= 1) {
        if (tid < st) sD[tid] += sD[tid + st];
        __syncthreads();
    }
    if (tid == 0 && out_size >= 133122) {
        float m = (float)(sD[0] / 131072.0);
        out[131072] = m;
        out[131073] = m;
    }
}

// ---------------------------------------------------------------------------
extern "C" void kernel_launch(void* const* d_in, const int* in_sizes, int n_in,
                              void* d_out, int out_size) {
    const float* z = (const float*)d_in[0];
    const float* emb = (const float*)d_in[1];
    if (n_in >= 2 && in_sizes[0] == K_CODES * C_DIM && in_sizes[1] == N_ROWS * C_DIM) {
        const float* t = z; z = emb; emb = t;
    }
    float* out = (float*)d_out;

    cudaFuncSetAttribute(vq_mma_pass,
                         cudaFuncAttributeMaxDynamicSharedMemorySize, 57344);

    vq_prep<<<(K_CODES + N_ROWS) / PREP_ROWS, 256>>>(z, emb);
    vq_mma_pass<<<dim3(N_ROWS / M_TILE, NCHUNKS_SEED), 256, 57344>>>(0);
    vq_mma_pass<<<dim3(N_ROWS / M_TILE, NCHUNKS), 256, 57344>>>(1);
    vq_rescore_finalize<<<N_ROWS / 2, 256>>>(z, emb, out, out_size);
    vq_loss<<<1, 256>>>(out, out_size);
}